// round 4
// baseline (speedup 1.0000x reference)
#include <cuda_runtime.h>
#include <math.h>

// Problem constants
#define BB   128      // batch
#define TT   1024     // seq len
#define VV   256      // vocab
#define EE   128      // embedding
#define HH   1024     // hidden
#define DD   512      // dense
#define SS   5        // sentiments
#define G4H  4096     // 4*H

#define NCTA 128      // persistent grid: 32 col-tiles x 4 K-chunks
#define KCH  256      // K per chunk
#define CPT  128      // cols per tile (32 hidden units x 4 gates)

// ---------------- device scratch (allocation-free: __device__ globals) -------------------
__device__ float g_a2tab[VV * SS];
__device__ float g_gx_tab[VV * G4H];          // emb@Wih[:, :E]^T + bih + bhh  (per token)
__device__ float g_attn_tab[VV * G4H];        // a2@Wih[:, E:]^T               (per prev token)
__device__ float g_Wcomb[VV * HH];            // Wo @ Wd
__device__ float g_bcomb[VV];
__device__ float g_h0[BB * HH];
__device__ float g_part[NCTA * BB * CPT];     // split-K partials, indexed by CTA id (kg*32+jt)
__device__ float g_hs[(size_t)TT * BB * HH];  // hidden history [t][b][h]
__device__ unsigned g_count;
__device__ volatile unsigned g_gen;

__device__ __forceinline__ float sigm(float x) { return 1.0f / (1.0f + __expf(-x)); }

// ---------------- prep 1: senti tables (token-pure) --------------------------------------
__global__ void senti_tab_kernel(const float* __restrict__ emb,
                                 const float* __restrict__ s1_Wih, const float* __restrict__ s1_bih,
                                 const float* __restrict__ s1_bhh, const float* __restrict__ s1_Wd,
                                 const float* __restrict__ s1_bd,
                                 const float* __restrict__ s2_Wih, const float* __restrict__ s2_bih,
                                 const float* __restrict__ s2_bhh, const float* __restrict__ s2_Wd,
                                 const float* __restrict__ s2_bd) {
    int v = blockIdx.x * blockDim.x + threadIdx.x;
    if (v >= VV) return;

    float h1[8];
    {
        float g[32];
        const float* e = emb + v * EE;
        for (int j = 0; j < 32; j++) {
            const float* w = s1_Wih + j * EE;
            float a = s1_bih[j] + s1_bhh[j];
            for (int k = 0; k < EE; k++) a += e[k] * w[k];
            g[j] = a;
        }
        for (int u = 0; u < 8; u++) {
            float cc = sigm(g[u]) * tanhf(g[16 + u]);
            h1[u] = sigm(g[24 + u]) * tanhf(cc);
        }
    }
    float a1[SS];
    {
        float l[SS], m = -1e30f;
        for (int s = 0; s < SS; s++) {
            float a = s1_bd[s];
            for (int u = 0; u < 8; u++) a += h1[u] * s1_Wd[s * 8 + u];
            l[s] = a; m = fmaxf(m, a);
        }
        float sum = 0.0f;
        for (int s = 0; s < SS; s++) { l[s] = __expf(l[s] - m); sum += l[s]; }
        for (int s = 0; s < SS; s++) a1[s] = l[s] / sum;
    }
    float h2[8];
    {
        float g[32];
        for (int j = 0; j < 32; j++) {
            const float* w = s2_Wih + j * SS;
            float a = s2_bih[j] + s2_bhh[j];
            for (int s = 0; s < SS; s++) a += a1[s] * w[s];
            g[j] = a;
        }
        for (int u = 0; u < 8; u++) {
            float cc = sigm(g[u]) * tanhf(g[16 + u]);
            h2[u] = sigm(g[24 + u]) * tanhf(cc);
        }
    }
    {
        float l[SS], m = -1e30f;
        for (int s = 0; s < SS; s++) {
            float a = s2_bd[s];
            for (int u = 0; u < 8; u++) a += h2[u] * s2_Wd[s * 8 + u];
            l[s] = a; m = fmaxf(m, a);
        }
        float sum = 0.0f;
        for (int s = 0; s < SS; s++) { l[s] = __expf(l[s] - m); sum += l[s]; }
        for (int s = 0; s < SS; s++) g_a2tab[v * SS + s] = l[s] / sum;
    }
}

// ---------------- prep 2: per-token gate-input tables ------------------------------------
__global__ __launch_bounds__(256) void tab_kernel(const float* __restrict__ emb,
                                                  const float* __restrict__ Wih,
                                                  const float* __restrict__ bih,
                                                  const float* __restrict__ bhh) {
    int v = blockIdx.x;
    __shared__ float se[EE];
    __shared__ float sa[SS];
    if (threadIdx.x < EE) se[threadIdx.x] = emb[v * EE + threadIdx.x];
    if (threadIdx.x < SS) sa[threadIdx.x] = g_a2tab[v * SS + threadIdx.x];
    __syncthreads();
    for (int j = threadIdx.x; j < G4H; j += 256) {
        const float* w = Wih + (size_t)j * (EE + SS);
        float a = bih[j] + bhh[j];
        for (int k = 0; k < EE; k++) a += se[k] * w[k];
        g_gx_tab[v * G4H + j] = a;
        float at = 0.0f;
        for (int s = 0; s < SS; s++) at += sa[s] * w[EE + s];
        g_attn_tab[v * G4H + j] = at;
    }
}

// ---------------- prep 3: Wcomb = Wo @ Wd ------------------------------------------------
__global__ __launch_bounds__(256) void wcomb_kernel(const float* __restrict__ Wd,
                                                    const float* __restrict__ bd,
                                                    const float* __restrict__ Wo,
                                                    const float* __restrict__ bo) {
    int o = blockIdx.x;
    __shared__ float swo[DD];
    for (int i = threadIdx.x; i < DD; i += 256) swo[i] = Wo[o * DD + i];
    __syncthreads();
    for (int k = threadIdx.x; k < HH; k += 256) {
        float a = 0.0f;
        for (int d = 0; d < DD; d++) a += swo[d] * Wd[d * HH + k];
        g_Wcomb[o * HH + k] = a;
    }
    if (threadIdx.x == 0) {
        float a = bo[o];
        for (int d = 0; d < DD; d++) a += swo[d] * bd[d];
        g_bcomb[o] = a;
    }
}

// ---------------- prep 4: zero initial state + barrier reset -----------------------------
__global__ void init_kernel() {
    int idx = blockIdx.x * blockDim.x + threadIdx.x;
    if (idx < BB * HH) g_h0[idx] = 0.0f;
    if (idx == 0) { g_count = 0; g_gen = 0; }
}

// ---------------- global software barrier (all NCTA CTAs co-resident) --------------------
__device__ __forceinline__ void gbar(unsigned target) {
    __syncthreads();
    if (threadIdx.x == 0) {
        __threadfence();
        unsigned prev = atomicAdd(&g_count, 1);
        if (prev == NCTA - 1) {
            g_count = 0;
            __threadfence();
            g_gen = target;
        } else {
            while (g_gen < target) __nanosleep(32);
        }
        __threadfence();
    }
    __syncthreads();
}

// ---------------- persistent recurrence kernel -------------------------------------------
// 128 CTAs x 256 threads. CTA (jt = bx%32, kg = bx/32):
//   smem-resident Whh slice: cols jt-tile (32 units x 4 gates), K-chunk kg (256)
//   phase 1: partial GEMM  part[b in 0..127][c in 0..127] over K-chunk
//   phase 2: reduce 4 partials + LSTM pointwise for batch group kg (32 b) x 32 units
__global__ __launch_bounds__(256, 1) void rnn_kernel(const int* __restrict__ x,
                                                     const float* __restrict__ Whh) {
    extern __shared__ float smem[];
    float* Bs = smem;                 // [256][132]  Whh slice (persistent)
    float* As = smem + KCH * 132;     // [32][132]   h sub-tile

    const int tid = threadIdx.x;
    const int jt = blockIdx.x & 31;
    const int kg = blockIdx.x >> 5;
    const int kc0 = kg * KCH;

    // ---- load Whh slice into smem once: Bs[kk][c], c = gate*32 + u
#pragma unroll 4
    for (int i = 0; i < 128; i++) {
        int idx = tid + (i << 8);
        int c = idx >> 8;             // == i
        int kk = idx & 255;           // == tid
        int j = ((c >> 5) << 10) + (jt << 5) + (c & 31);   // gate*1024 + jt*32 + u
        Bs[kk * 132 + c] = Whh[(size_t)j * HH + kc0 + kk];
    }

    const int tx = tid & 15;          // col group (x8)
    const int ty = tid >> 4;          // row group (x8)
    const int r0 = ty << 3;
    const int c0 = tx << 3;
    float* partmine = g_part + ((size_t)blockIdx.x * BB) * CPT;

    // phase-2 ownership: batches kg*32..+31, hidden units jt*32..+31
    const int u = tid & 31;
    const int bloc = tid >> 5;        // 0..7
    const int uglob = (jt << 5) + u;
    float creg[4] = {0.f, 0.f, 0.f, 0.f};    // cell state, register-resident

    gbar(1);

    for (int t = 0; t < TT; t++) {
        const float* hprev = (t == 0) ? g_h0 : (g_hs + (size_t)(t - 1) * BB * HH);

        // ================= phase 1: partial GEMM =================
        float acc[8][8];
#pragma unroll
        for (int r = 0; r < 8; r++)
#pragma unroll
            for (int c = 0; c < 8; c++) acc[r][c] = 0.f;

        for (int kcs = 0; kcs < KCH; kcs += 32) {
#pragma unroll
            for (int i = 0; i < 16; i++) {
                int idx = tid + (i << 8);
                int b = idx >> 5, kk = idx & 31;
                As[kk * 132 + b] = hprev[(size_t)b * HH + kc0 + kcs + kk];
            }
            __syncthreads();
#pragma unroll
            for (int kk = 0; kk < 32; kk++) {
                float4 a0 = *(const float4*)&As[kk * 132 + r0];
                float4 a1 = *(const float4*)&As[kk * 132 + r0 + 4];
                float4 b0 = *(const float4*)&Bs[(kcs + kk) * 132 + c0];
                float4 b1 = *(const float4*)&Bs[(kcs + kk) * 132 + c0 + 4];
                float ar[8] = {a0.x, a0.y, a0.z, a0.w, a1.x, a1.y, a1.z, a1.w};
                float br[8] = {b0.x, b0.y, b0.z, b0.w, b1.x, b1.y, b1.z, b1.w};
#pragma unroll
                for (int r = 0; r < 8; r++)
#pragma unroll
                    for (int c = 0; c < 8; c++) acc[r][c] += ar[r] * br[c];
            }
            __syncthreads();
        }
        // write partials (L2-coherent: .cg, buffer is reused every step)
#pragma unroll
        for (int r = 0; r < 8; r++) {
            float* dst = partmine + (size_t)(r0 + r) * CPT + c0;
            float4 v0 = make_float4(acc[r][0], acc[r][1], acc[r][2], acc[r][3]);
            float4 v1 = make_float4(acc[r][4], acc[r][5], acc[r][6], acc[r][7]);
            __stcg((float4*)dst, v0);
            __stcg((float4*)(dst + 4), v1);
        }

        gbar((unsigned)(2 * t + 2));

        // ================= phase 2: reduce + LSTM pointwise =================
        // partials for column-tile jt live at CTA ids {0,1,2,3}*32 + jt
        float* hcur = g_hs + (size_t)t * BB * HH;
#pragma unroll
        for (int i = 0; i < 4; i++) {
            int b = (kg << 5) + bloc + (i << 3);
            int tok = __ldg(&x[b * TT + t]);
            const float* gx = g_gx_tab + (size_t)tok * G4H;
            float g[4];
#pragma unroll
            for (int gate = 0; gate < 4; gate++) {
                int c = (gate << 5) + u;
                const float* p = g_part + ((size_t)jt * BB + b) * CPT + c;   // chunk 0 (CTA jt)
                const size_t cs = (size_t)32 * BB * CPT;                     // chunk stride
                float s = __ldcg(p) + __ldcg(p + cs) +
                          __ldcg(p + 2 * cs) + __ldcg(p + 3 * cs);
                s += gx[(gate << 10) + uglob];
                g[gate] = s;
            }
            if (t > 0) {
                int pt = __ldg(&x[b * TT + t - 1]);
                const float* at = g_attn_tab + (size_t)pt * G4H;
#pragma unroll
                for (int gate = 0; gate < 4; gate++) g[gate] += at[(gate << 10) + uglob];
            }
            float cn = sigm(g[1]) * creg[i] + sigm(g[0]) * tanhf(g[2]);
            float hn = sigm(g[3]) * tanhf(cn);
            creg[i] = cn;
            hcur[(size_t)b * HH + uglob] = hn;
        }

        gbar((unsigned)(2 * t + 3));
    }
}

// ---------------- epilogue: logits = hs @ Wcomb^T + bcomb, then log_softmax --------------
__global__ __launch_bounds__(256) void out_kernel(float* __restrict__ out) {
    const int r0 = blockIdx.x << 5;
    __shared__ float A[32][36];
    __shared__ float Wsh[32 * 260];

    const int tid = threadIdx.x;
    const int tx = tid & 31, ty = tid >> 5;
    float acc[4][8] = {};

    for (int kc = 0; kc < HH; kc += 32) {
#pragma unroll
        for (int i = 0; i < 4; i++) {
            int idx = tid + (i << 8);
            int rr = idx >> 5, kk = idx & 31;
            A[kk][rr] = g_hs[(size_t)(r0 + rr) * HH + kc + kk];
        }
#pragma unroll
        for (int i = 0; i < 32; i++) {
            int idx = tid + (i << 8);
            int col = idx >> 5, kk = idx & 31;
            Wsh[kk * 260 + col] = g_Wcomb[(size_t)col * HH + kc + kk];
        }
        __syncthreads();
#pragma unroll
        for (int kk = 0; kk < 32; kk++) {
            float4 a4 = *(const float4*)&A[kk][ty << 2];
            float4 w0 = *(const float4*)&Wsh[kk * 260 + (tx << 3)];
            float4 w1 = *(const float4*)&Wsh[kk * 260 + (tx << 3) + 4];
            float ar[4] = {a4.x, a4.y, a4.z, a4.w};
            float wr[8] = {w0.x, w0.y, w0.z, w0.w, w1.x, w1.y, w1.z, w1.w};
#pragma unroll
            for (int r = 0; r < 4; r++)
#pragma unroll
                for (int c = 0; c < 8; c++) acc[r][c] += ar[r] * wr[c];
        }
        __syncthreads();
    }

#pragma unroll
    for (int r = 0; r < 4; r++)
#pragma unroll
        for (int c = 0; c < 8; c++) {
            int col = (tx << 3) + c;
            Wsh[((ty << 2) + r) * 260 + col] = acc[r][c] + g_bcomb[col];
        }
    __syncthreads();

    const int lane = tx;
#pragma unroll
    for (int rr = (ty << 2); rr < (ty << 2) + 4; rr++) {
        const float* row = &Wsh[rr * 260];
        float m = -1e30f;
#pragma unroll
        for (int q = 0; q < 8; q++) m = fmaxf(m, row[lane + (q << 5)]);
#pragma unroll
        for (int off = 16; off > 0; off >>= 1) m = fmaxf(m, __shfl_xor_sync(0xffffffffu, m, off));
        float s = 0.0f;
#pragma unroll
        for (int q = 0; q < 8; q++) s += __expf(row[lane + (q << 5)] - m);
#pragma unroll
        for (int off = 16; off > 0; off >>= 1) s += __shfl_xor_sync(0xffffffffu, s, off);
        float lse = m + logf(s);
        int r = r0 + rr;
        int tcur = r >> 7;
        int bcur = r & 127;
        float* dst = out + (((size_t)bcur * TT + tcur) << 8);
#pragma unroll
        for (int q = 0; q < 8; q++) {
            int vv = lane + (q << 5);
            dst[vv] = row[vv] - lse;
        }
    }
}

// -----------------------------------------------------------------------------------------
extern "C" void kernel_launch(void* const* d_in, const int* in_sizes, int n_in,
                              void* d_out, int out_size) {
    const int*   x        = (const int*)  d_in[0];
    const float* emb      = (const float*)d_in[1];
    const float* lstm_Wih = (const float*)d_in[2];
    const float* lstm_Whh = (const float*)d_in[3];
    const float* lstm_bih = (const float*)d_in[4];
    const float* lstm_bhh = (const float*)d_in[5];
    const float* Wd       = (const float*)d_in[6];
    const float* bd       = (const float*)d_in[7];
    const float* Wo       = (const float*)d_in[8];
    const float* bo       = (const float*)d_in[9];
    const float* s1_Wih   = (const float*)d_in[10];
    const float* s1_bih   = (const float*)d_in[11];
    const float* s1_bhh   = (const float*)d_in[12];
    const float* s1_Wd    = (const float*)d_in[13];
    const float* s1_bd    = (const float*)d_in[14];
    const float* s2_Wih   = (const float*)d_in[15];
    const float* s2_bih   = (const float*)d_in[16];
    const float* s2_bhh   = (const float*)d_in[17];
    const float* s2_Wd    = (const float*)d_in[18];
    const float* s2_bd    = (const float*)d_in[19];
    float* out = (float*)d_out;

    cudaFuncSetAttribute(rnn_kernel, cudaFuncAttributeMaxDynamicSharedMemorySize,
                         (KCH * 132 + 32 * 132) * sizeof(float));

    senti_tab_kernel<<<1, 256>>>(emb, s1_Wih, s1_bih, s1_bhh, s1_Wd, s1_bd,
                                 s2_Wih, s2_bih, s2_bhh, s2_Wd, s2_bd);
    tab_kernel<<<VV, 256>>>(emb, lstm_Wih, lstm_bih, lstm_bhh);
    wcomb_kernel<<<VV, 256>>>(Wd, bd, Wo, bo);
    init_kernel<<<(BB * HH + 255) / 256, 256>>>();

    rnn_kernel<<<NCTA, 256, (KCH * 132 + 32 * 132) * sizeof(float)>>>(x, lstm_Whh);

    out_kernel<<<(TT * BB) / 32, 256>>>(out);
}

// round 5
// speedup vs baseline: 1.3692x; 1.3692x over previous
#include <cuda_runtime.h>
#include <math.h>
#include <stdint.h>

// Problem constants
#define BB   128      // batch
#define TT   1024     // seq len
#define VV   256      // vocab
#define EE   128      // embedding
#define HH   1024     // hidden
#define DD   512      // dense
#define SS   5        // sentiments
#define G4H  4096     // 4*H

#define NCTA 128      // persistent grid: CTA jt owns units jt*8..jt*8+7 (x 4 gates = 32 cols)

// ---------------- device scratch (allocation-free: __device__ globals) -------------------
__device__ float g_a2tab[VV * SS];
__device__ float g_gx_tab[VV * G4H];          // emb@Wih[:, :E]^T + bih + bhh  (per token)
__device__ float g_attn_tab[VV * G4H];        // a2@Wih[:, E:]^T               (per prev token)
__device__ float g_Wcomb[VV * HH];            // Wo @ Wd
__device__ float g_bcomb[VV];
__device__ float g_h0[BB * HH];
__device__ float g_hs[(size_t)TT * BB * HH];  // hidden history [t][b][h]
__device__ unsigned g_count;
__device__ volatile unsigned g_gen;

__device__ __forceinline__ float sigm(float x) { return 1.0f / (1.0f + __expf(-x)); }

__device__ __forceinline__ uint32_t f2tf32(float f) {
    uint32_t u;
    asm("cvt.rna.tf32.f32 %0, %1;" : "=r"(u) : "f"(f));
    return u;
}

// ---------------- prep 1: senti tables (token-pure) --------------------------------------
__global__ void senti_tab_kernel(const float* __restrict__ emb,
                                 const float* __restrict__ s1_Wih, const float* __restrict__ s1_bih,
                                 const float* __restrict__ s1_bhh, const float* __restrict__ s1_Wd,
                                 const float* __restrict__ s1_bd,
                                 const float* __restrict__ s2_Wih, const float* __restrict__ s2_bih,
                                 const float* __restrict__ s2_bhh, const float* __restrict__ s2_Wd,
                                 const float* __restrict__ s2_bd) {
    int v = blockIdx.x * blockDim.x + threadIdx.x;
    if (v >= VV) return;

    float h1[8];
    {
        float g[32];
        const float* e = emb + v * EE;
        for (int j = 0; j < 32; j++) {
            const float* w = s1_Wih + j * EE;
            float a = s1_bih[j] + s1_bhh[j];
            for (int k = 0; k < EE; k++) a += e[k] * w[k];
            g[j] = a;
        }
        for (int u = 0; u < 8; u++) {
            float cc = sigm(g[u]) * tanhf(g[16 + u]);
            h1[u] = sigm(g[24 + u]) * tanhf(cc);
        }
    }
    float a1[SS];
    {
        float l[SS], m = -1e30f;
        for (int s = 0; s < SS; s++) {
            float a = s1_bd[s];
            for (int u = 0; u < 8; u++) a += h1[u] * s1_Wd[s * 8 + u];
            l[s] = a; m = fmaxf(m, a);
        }
        float sum = 0.0f;
        for (int s = 0; s < SS; s++) { l[s] = __expf(l[s] - m); sum += l[s]; }
        for (int s = 0; s < SS; s++) a1[s] = l[s] / sum;
    }
    float h2[8];
    {
        float g[32];
        for (int j = 0; j < 32; j++) {
            const float* w = s2_Wih + j * SS;
            float a = s2_bih[j] + s2_bhh[j];
            for (int s = 0; s < SS; s++) a += a1[s] * w[s];
            g[j] = a;
        }
        for (int u = 0; u < 8; u++) {
            float cc = sigm(g[u]) * tanhf(g[16 + u]);
            h2[u] = sigm(g[24 + u]) * tanhf(cc);
        }
    }
    {
        float l[SS], m = -1e30f;
        for (int s = 0; s < SS; s++) {
            float a = s2_bd[s];
            for (int u = 0; u < 8; u++) a += h2[u] * s2_Wd[s * 8 + u];
            l[s] = a; m = fmaxf(m, a);
        }
        float sum = 0.0f;
        for (int s = 0; s < SS; s++) { l[s] = __expf(l[s] - m); sum += l[s]; }
        for (int s = 0; s < SS; s++) g_a2tab[v * SS + s] = l[s] / sum;
    }
}

// ---------------- prep 2: per-token gate-input tables ------------------------------------
__global__ __launch_bounds__(256) void tab_kernel(const float* __restrict__ emb,
                                                  const float* __restrict__ Wih,
                                                  const float* __restrict__ bih,
                                                  const float* __restrict__ bhh) {
    int v = blockIdx.x;
    __shared__ float se[EE];
    __shared__ float sa[SS];
    if (threadIdx.x < EE) se[threadIdx.x] = emb[v * EE + threadIdx.x];
    if (threadIdx.x < SS) sa[threadIdx.x] = g_a2tab[v * SS + threadIdx.x];
    __syncthreads();
    for (int j = threadIdx.x; j < G4H; j += 256) {
        const float* w = Wih + (size_t)j * (EE + SS);
        float a = bih[j] + bhh[j];
        for (int k = 0; k < EE; k++) a += se[k] * w[k];
        g_gx_tab[v * G4H + j] = a;
        float at = 0.0f;
        for (int s = 0; s < SS; s++) at += sa[s] * w[EE + s];
        g_attn_tab[v * G4H + j] = at;
    }
}

// ---------------- prep 3: Wcomb = Wo @ Wd ------------------------------------------------
__global__ __launch_bounds__(256) void wcomb_kernel(const float* __restrict__ Wd,
                                                    const float* __restrict__ bd,
                                                    const float* __restrict__ Wo,
                                                    const float* __restrict__ bo) {
    int o = blockIdx.x;
    __shared__ float swo[DD];
    for (int i = threadIdx.x; i < DD; i += 256) swo[i] = Wo[o * DD + i];
    __syncthreads();
    for (int k = threadIdx.x; k < HH; k += 256) {
        float a = 0.0f;
        for (int d = 0; d < DD; d++) a += swo[d] * Wd[d * HH + k];
        g_Wcomb[o * HH + k] = a;
    }
    if (threadIdx.x == 0) {
        float a = bo[o];
        for (int d = 0; d < DD; d++) a += swo[d] * bd[d];
        g_bcomb[o] = a;
    }
}

// ---------------- prep 4: zero initial state + barrier reset -----------------------------
__global__ void init_kernel() {
    int idx = blockIdx.x * blockDim.x + threadIdx.x;
    if (idx < BB * HH) g_h0[idx] = 0.0f;
    if (idx == 0) { g_count = 0; g_gen = 0; }
}

// ---------------- global software barrier (all NCTA CTAs co-resident) --------------------
__device__ __forceinline__ void gbar(unsigned target) {
    __syncthreads();
    if (threadIdx.x == 0) {
        __threadfence();
        unsigned prev = atomicAdd(&g_count, 1);
        if (prev == NCTA - 1) {
            g_count = 0;
            __threadfence();
            g_gen = target;
        } else {
            while (g_gen < target) __nanosleep(32);
        }
        __threadfence();
    }
    __syncthreads();
}

// ---------------- persistent recurrence kernel (tf32 tensor cores) -----------------------
// 128 CTAs x 256 threads (8 warps). CTA jt:
//   columns c = gate*8 + uu  (uu in 0..7), mapping to Whh row j = gate*1024 + jt*8 + uu
//   B (Whh slice, 1024K x 32cols) pre-packed in smem in MMA fragment order (tf32-rounded)
//   per step: C[128b x 32c] = hprev[128,1024] @ Wslice via mma.sync m16n8k8 tf32
//             warp w handles rows 16w..16w+15, all 4 n-blocks (gates)
//   k-permutation: fragment k-position {tig, tig+4} <-> physical k {2tig, 2tig+1}
//   (applied identically to A loads and B pack; contraction order-independent)
//   then CTA-local LSTM pointwise for its 8 units x 128 batches, ONE gbar per step.
__global__ __launch_bounds__(256, 1) void rnn2_kernel(const int* __restrict__ x,
                                                      const float* __restrict__ Whh) {
    extern __shared__ float smem[];
    float2* Bf = (float2*)smem;               // [128kb][4nb][32lane] float2 = 128KB
    float*  Cs = smem + 32768;                // [128][36] = 18KB

    const int tid  = threadIdx.x;
    const int jt   = blockIdx.x;              // 0..127
    const int lane = tid & 31;
    const int w    = tid >> 5;
    const int g    = lane >> 2;               // 0..7
    const int tig  = lane & 3;                // 0..3

    // ---- pack Whh slice into fragment order, tf32-rounded (once per launch) ----
    for (int i = tid; i < 16384; i += 256) {
        int L  = i & 31;
        int nb = (i >> 5) & 3;
        int kb = i >> 7;
        int gg = L >> 2, tt = L & 3;
        int j  = nb * 1024 + jt * 8 + gg;     // Whh row for column (gate=nb, uu=gg)
        int k0 = kb * 8 + 2 * tt;
        float w0 = Whh[(size_t)j * HH + k0];
        float w1 = Whh[(size_t)j * HH + k0 + 1];
        Bf[i] = make_float2(__uint_as_float(f2tf32(w0)), __uint_as_float(f2tf32(w1)));
    }

    float creg[4] = {0.f, 0.f, 0.f, 0.f};    // cell state: pairs idx = tid*4+p

    gbar(1);

    const int r0 = w * 16;
    for (int t = 0; t < TT; t++) {
        const float* hprev = (t == 0) ? g_h0 : (g_hs + (size_t)(t - 1) * BB * HH);

        float acc[4][4];
#pragma unroll
        for (int nb = 0; nb < 4; nb++)
#pragma unroll
            for (int q = 0; q < 4; q++) acc[nb][q] = 0.f;

        const float2* arow0 = (const float2*)(hprev + (size_t)(r0 + g) * HH);
        const float2* arow1 = (const float2*)(hprev + (size_t)(r0 + g + 8) * HH);

#pragma unroll 4
        for (int kb = 0; kb < 128; kb++) {
            float2 aLo = __ldcg(&arow0[kb * 4 + tig]);   // (row g,   k=2tig / 2tig+1)
            float2 aHi = __ldcg(&arow1[kb * 4 + tig]);   // (row g+8, ...)
            uint32_t a0 = f2tf32(aLo.x);
            uint32_t a2 = f2tf32(aLo.y);
            uint32_t a1 = f2tf32(aHi.x);
            uint32_t a3 = f2tf32(aHi.y);
            const float2* bptr = &Bf[(kb * 4) * 32 + lane];
#pragma unroll
            for (int nb = 0; nb < 4; nb++) {
                float2 bv = bptr[nb * 32];
                uint32_t b0 = __float_as_uint(bv.x);
                uint32_t b1 = __float_as_uint(bv.y);
                asm volatile(
                    "mma.sync.aligned.m16n8k8.row.col.f32.tf32.tf32.f32 "
                    "{%0,%1,%2,%3}, {%4,%5,%6,%7}, {%8,%9}, {%0,%1,%2,%3};"
                    : "+f"(acc[nb][0]), "+f"(acc[nb][1]), "+f"(acc[nb][2]), "+f"(acc[nb][3])
                    : "r"(a0), "r"(a1), "r"(a2), "r"(a3), "r"(b0), "r"(b1));
            }
        }

        // ---- write C tile to smem: Cs[b][col], col = nb*8 + {2tig, 2tig+1}
#pragma unroll
        for (int nb = 0; nb < 4; nb++) {
            *(float2*)&Cs[(r0 + g)     * 36 + nb * 8 + 2 * tig] = make_float2(acc[nb][0], acc[nb][1]);
            *(float2*)&Cs[(r0 + g + 8) * 36 + nb * 8 + 2 * tig] = make_float2(acc[nb][2], acc[nb][3]);
        }
        __syncthreads();

        // ---- LSTM pointwise: 128 batches x 8 units, 4 (b,u) pairs per thread
        float* hcur = g_hs + (size_t)t * BB * HH;
#pragma unroll
        for (int p = 0; p < 4; p++) {
            int idx = (tid << 2) + p;
            int b = idx >> 3, uu = idx & 7;
            int tok = __ldg(&x[b * TT + t]);
            const float* gx = g_gx_tab + (size_t)tok * G4H + jt * 8 + uu;
            float gi = Cs[b * 36 +  0 + uu] + __ldg(gx);
            float gf = Cs[b * 36 +  8 + uu] + __ldg(gx + HH);
            float gg = Cs[b * 36 + 16 + uu] + __ldg(gx + 2 * HH);
            float go = Cs[b * 36 + 24 + uu] + __ldg(gx + 3 * HH);
            if (t > 0) {
                int pt = __ldg(&x[b * TT + t - 1]);
                const float* at = g_attn_tab + (size_t)pt * G4H + jt * 8 + uu;
                gi += __ldg(at); gf += __ldg(at + HH);
                gg += __ldg(at + 2 * HH); go += __ldg(at + 3 * HH);
            }
            float cn = sigm(gf) * creg[p] + sigm(gi) * tanhf(gg);
            float hn = sigm(go) * tanhf(cn);
            creg[p] = cn;
            hcur[(size_t)b * HH + jt * 8 + uu] = hn;
        }

        gbar((unsigned)(t + 2));   // includes __syncthreads: protects Cs reuse too
    }
}

// ---------------- epilogue: logits = hs @ Wcomb^T + bcomb, then log_softmax --------------
__global__ __launch_bounds__(256) void out_kernel(float* __restrict__ out) {
    const int r0 = blockIdx.x << 5;
    __shared__ float A[32][36];
    __shared__ float Wsh[32 * 260];

    const int tid = threadIdx.x;
    const int tx = tid & 31, ty = tid >> 5;
    float acc[4][8] = {};

    for (int kc = 0; kc < HH; kc += 32) {
#pragma unroll
        for (int i = 0; i < 4; i++) {
            int idx = tid + (i << 8);
            int rr = idx >> 5, kk = idx & 31;
            A[kk][rr] = g_hs[(size_t)(r0 + rr) * HH + kc + kk];
        }
#pragma unroll
        for (int i = 0; i < 32; i++) {
            int idx = tid + (i << 8);
            int col = idx >> 5, kk = idx & 31;
            Wsh[kk * 260 + col] = g_Wcomb[(size_t)col * HH + kc + kk];
        }
        __syncthreads();
#pragma unroll
        for (int kk = 0; kk < 32; kk++) {
            float4 a4 = *(const float4*)&A[kk][ty << 2];
            float4 w0 = *(const float4*)&Wsh[kk * 260 + (tx << 3)];
            float4 w1 = *(const float4*)&Wsh[kk * 260 + (tx << 3) + 4];
            float ar[4] = {a4.x, a4.y, a4.z, a4.w};
            float wr[8] = {w0.x, w0.y, w0.z, w0.w, w1.x, w1.y, w1.z, w1.w};
#pragma unroll
            for (int r = 0; r < 4; r++)
#pragma unroll
                for (int c = 0; c < 8; c++) acc[r][c] += ar[r] * wr[c];
        }
        __syncthreads();
    }

#pragma unroll
    for (int r = 0; r < 4; r++)
#pragma unroll
        for (int c = 0; c < 8; c++) {
            int col = (tx << 3) + c;
            Wsh[((ty << 2) + r) * 260 + col] = acc[r][c] + g_bcomb[col];
        }
    __syncthreads();

    const int lane = tx;
#pragma unroll
    for (int rr = (ty << 2); rr < (ty << 2) + 4; rr++) {
        const float* row = &Wsh[rr * 260];
        float m = -1e30f;
#pragma unroll
        for (int q = 0; q < 8; q++) m = fmaxf(m, row[lane + (q << 5)]);
#pragma unroll
        for (int off = 16; off > 0; off >>= 1) m = fmaxf(m, __shfl_xor_sync(0xffffffffu, m, off));
        float s = 0.0f;
#pragma unroll
        for (int q = 0; q < 8; q++) s += __expf(row[lane + (q << 5)] - m);
#pragma unroll
        for (int off = 16; off > 0; off >>= 1) s += __shfl_xor_sync(0xffffffffu, s, off);
        float lse = m + logf(s);
        int r = r0 + rr;
        int tcur = r >> 7;
        int bcur = r & 127;
        float* dst = out + (((size_t)bcur * TT + tcur) << 8);
#pragma unroll
        for (int q = 0; q < 8; q++) {
            int vv = lane + (q << 5);
            dst[vv] = row[vv] - lse;
        }
    }
}

// -----------------------------------------------------------------------------------------
extern "C" void kernel_launch(void* const* d_in, const int* in_sizes, int n_in,
                              void* d_out, int out_size) {
    const int*   x        = (const int*)  d_in[0];
    const float* emb      = (const float*)d_in[1];
    const float* lstm_Wih = (const float*)d_in[2];
    const float* lstm_Whh = (const float*)d_in[3];
    const float* lstm_bih = (const float*)d_in[4];
    const float* lstm_bhh = (const float*)d_in[5];
    const float* Wd       = (const float*)d_in[6];
    const float* bd       = (const float*)d_in[7];
    const float* Wo       = (const float*)d_in[8];
    const float* bo       = (const float*)d_in[9];
    const float* s1_Wih   = (const float*)d_in[10];
    const float* s1_bih   = (const float*)d_in[11];
    const float* s1_bhh   = (const float*)d_in[12];
    const float* s1_Wd    = (const float*)d_in[13];
    const float* s1_bd    = (const float*)d_in[14];
    const float* s2_Wih   = (const float*)d_in[15];
    const float* s2_bih   = (const float*)d_in[16];
    const float* s2_bhh   = (const float*)d_in[17];
    const float* s2_Wd    = (const float*)d_in[18];
    const float* s2_bd    = (const float*)d_in[19];
    float* out = (float*)d_out;

    const int smem_bytes = 32768 * 4 + 128 * 36 * 4;   // Bf 128KB + Cs 18KB
    cudaFuncSetAttribute(rnn2_kernel, cudaFuncAttributeMaxDynamicSharedMemorySize, smem_bytes);

    senti_tab_kernel<<<1, 256>>>(emb, s1_Wih, s1_bih, s1_bhh, s1_Wd, s1_bd,
                                 s2_Wih, s2_bih, s2_bhh, s2_Wd, s2_bd);
    tab_kernel<<<VV, 256>>>(emb, lstm_Wih, lstm_bih, lstm_bhh);
    wcomb_kernel<<<VV, 256>>>(Wd, bd, Wo, bo);
    init_kernel<<<(BB * HH + 255) / 256, 256>>>();

    rnn2_kernel<<<NCTA, 256, smem_bytes>>>(x, lstm_Whh);

    out_kernel<<<(TT * BB) / 32, 256>>>(out);
}

// round 8
// speedup vs baseline: 2.4169x; 1.7652x over previous
#include <cuda_runtime.h>
#include <math.h>
#include <stdint.h>

// Problem constants
#define BB   128
#define TT   1024
#define VV   256
#define EE   128
#define HH   1024
#define DD   512
#define SS   5
#define G4H  4096
#define NCTA 128

// h-state in A-fragment layout: [t][kb 0..127][mt 0..7][lane 0..31][slot 0..3] floats
// slab per kb = 8*32*4 = 1024 floats (4KB); per t = 131072 floats (512KB)
#define HF_T 131072

// smem layout (byte offsets from 1024-aligned base)
#define SM_B   0               // B packed fragments: 128kb x 2np x 32L x 16B = 128KB
#define SM_A   131072          // A stages: 2 x 32KB (stage = 8 kb slabs)
#define SM_CS  196608          // C tile [128][36] floats = 18432B
#define SM_CTL 215040          // full0 +0, full1 +8, free0 +16, free1 +24
#define SM_TOTAL (215040 + 64)

// ---------------- device scratch -------------------------------------------------------
__device__ float g_a2tab[VV * SS];
__device__ float g_gx_tab[VV * G4H];
__device__ float g_attn_tab[VV * G4H];
__device__ float g_Wcomb[VV * HH];
__device__ float g_bcomb[VV];
__device__ float g_h0f[HF_T];                       // zeros, fragment layout
__device__ float g_hsf[(size_t)TT * HF_T];          // h history, fragment layout
__device__ unsigned g_count;
__device__ volatile unsigned g_gen;

__device__ __forceinline__ float sigm(float x) { return 1.0f / (1.0f + __expf(-x)); }
__device__ __forceinline__ uint32_t f2tf32(float f) {
    uint32_t u;
    asm("cvt.rna.tf32.f32 %0, %1;" : "=r"(u) : "f"(f));
    return u;
}
__device__ __forceinline__ uint32_t smem_u32(const void* p) {
    uint32_t a;
    asm("{ .reg .u64 t; cvta.to.shared.u64 t, %1; cvt.u32.u64 %0, t; }" : "=r"(a) : "l"(p));
    return a;
}

#define MBAR_INIT(a, n) asm volatile("mbarrier.init.shared.b64 [%0], %1;" :: "r"(a), "r"((uint32_t)(n)) : "memory")
#define MBAR_ARRIVE(a)  asm volatile("mbarrier.arrive.shared.b64 _, [%0];" :: "r"(a) : "memory")
#define MBAR_EXPECT_TX(a, b) asm volatile("mbarrier.arrive.expect_tx.shared.b64 _, [%0], %1;" :: "r"(a), "r"((uint32_t)(b)) : "memory")
#define MBAR_WAIT(a, par) do { \
    uint32_t _m = (a), _p = (par), _d; \
    asm volatile("{ .reg .pred p; mbarrier.try_wait.parity.acquire.cta.shared::cta.b64 p, [%1], %2; selp.b32 %0,1,0,p; }" \
                 : "=r"(_d) : "r"(_m), "r"(_p) : "memory"); \
    if (!_d) { \
        asm volatile("{ .reg .pred P1; WL_%=: mbarrier.try_wait.parity.acquire.cta.shared::cta.b64 P1, [%0], %1, 0x989680; " \
                     "@P1 bra.uni WD_%=; bra.uni WL_%=; WD_%=: }" :: "r"(_m), "r"(_p) : "memory"); \
    } } while (0)

#define BULK_CP(dst, src, bytes, mbar) \
    asm volatile("cp.async.bulk.shared::cluster.global.mbarrier::complete_tx::bytes [%0], [%1], %2, [%3];" \
                 :: "r"(dst), "l"(src), "r"((uint32_t)(bytes)), "r"(mbar) : "memory")

#define LDS128(r, addr) \
    asm volatile("ld.shared.v4.b32 {%0,%1,%2,%3}, [%4];" \
                 : "=r"((r)[0]), "=r"((r)[1]), "=r"((r)[2]), "=r"((r)[3]) : "r"(addr))

#define MMA_TF32(acc, a, b0, b1) \
    asm volatile("mma.sync.aligned.m16n8k8.row.col.f32.tf32.tf32.f32 " \
                 "{%0,%1,%2,%3}, {%4,%5,%6,%7}, {%8,%9}, {%0,%1,%2,%3};" \
                 : "+f"((acc)[0]), "+f"((acc)[1]), "+f"((acc)[2]), "+f"((acc)[3]) \
                 : "r"((a)[0]), "r"((a)[1]), "r"((a)[2]), "r"((a)[3]), "r"(b0), "r"(b1))

// ---------------- prep kernels ---------------------------------------------------------
__global__ void senti_tab_kernel(const float* __restrict__ emb,
                                 const float* __restrict__ s1_Wih, const float* __restrict__ s1_bih,
                                 const float* __restrict__ s1_bhh, const float* __restrict__ s1_Wd,
                                 const float* __restrict__ s1_bd,
                                 const float* __restrict__ s2_Wih, const float* __restrict__ s2_bih,
                                 const float* __restrict__ s2_bhh, const float* __restrict__ s2_Wd,
                                 const float* __restrict__ s2_bd) {
    int v = blockIdx.x * blockDim.x + threadIdx.x;
    if (v >= VV) return;
    float h1[8];
    {
        float g[32];
        const float* e = emb + v * EE;
        for (int j = 0; j < 32; j++) {
            const float* w = s1_Wih + j * EE;
            float a = s1_bih[j] + s1_bhh[j];
            for (int k = 0; k < EE; k++) a += e[k] * w[k];
            g[j] = a;
        }
        for (int u = 0; u < 8; u++) {
            float cc = sigm(g[u]) * tanhf(g[16 + u]);
            h1[u] = sigm(g[24 + u]) * tanhf(cc);
        }
    }
    float a1[SS];
    {
        float l[SS], m = -1e30f;
        for (int s = 0; s < SS; s++) {
            float a = s1_bd[s];
            for (int u = 0; u < 8; u++) a += h1[u] * s1_Wd[s * 8 + u];
            l[s] = a; m = fmaxf(m, a);
        }
        float sum = 0.0f;
        for (int s = 0; s < SS; s++) { l[s] = __expf(l[s] - m); sum += l[s]; }
        for (int s = 0; s < SS; s++) a1[s] = l[s] / sum;
    }
    float h2[8];
    {
        float g[32];
        for (int j = 0; j < 32; j++) {
            const float* w = s2_Wih + j * SS;
            float a = s2_bih[j] + s2_bhh[j];
            for (int s = 0; s < SS; s++) a += a1[s] * w[s];
            g[j] = a;
        }
        for (int u = 0; u < 8; u++) {
            float cc = sigm(g[u]) * tanhf(g[16 + u]);
            h2[u] = sigm(g[24 + u]) * tanhf(cc);
        }
    }
    {
        float l[SS], m = -1e30f;
        for (int s = 0; s < SS; s++) {
            float a = s2_bd[s];
            for (int u = 0; u < 8; u++) a += h2[u] * s2_Wd[s * 8 + u];
            l[s] = a; m = fmaxf(m, a);
        }
        float sum = 0.0f;
        for (int s = 0; s < SS; s++) { l[s] = __expf(l[s] - m); sum += l[s]; }
        for (int s = 0; s < SS; s++) g_a2tab[v * SS + s] = l[s] / sum;
    }
}

__global__ __launch_bounds__(256) void tab_kernel(const float* __restrict__ emb,
                                                  const float* __restrict__ Wih,
                                                  const float* __restrict__ bih,
                                                  const float* __restrict__ bhh) {
    int v = blockIdx.x;
    __shared__ float se[EE];
    __shared__ float sa[SS];
    if (threadIdx.x < EE) se[threadIdx.x] = emb[v * EE + threadIdx.x];
    if (threadIdx.x < SS) sa[threadIdx.x] = g_a2tab[v * SS + threadIdx.x];
    __syncthreads();
    for (int j = threadIdx.x; j < G4H; j += 256) {
        const float* w = Wih + (size_t)j * (EE + SS);
        float a = bih[j] + bhh[j];
        for (int k = 0; k < EE; k++) a += se[k] * w[k];
        g_gx_tab[v * G4H + j] = a;
        float at = 0.0f;
        for (int s = 0; s < SS; s++) at += sa[s] * w[EE + s];
        g_attn_tab[v * G4H + j] = at;
    }
}

__global__ __launch_bounds__(256) void wcomb_kernel(const float* __restrict__ Wd,
                                                    const float* __restrict__ bd,
                                                    const float* __restrict__ Wo,
                                                    const float* __restrict__ bo) {
    int o = blockIdx.x;
    __shared__ float swo[DD];
    for (int i = threadIdx.x; i < DD; i += 256) swo[i] = Wo[o * DD + i];
    __syncthreads();
    for (int k = threadIdx.x; k < HH; k += 256) {
        float a = 0.0f;
        for (int d = 0; d < DD; d++) a += swo[d] * Wd[d * HH + k];
        g_Wcomb[o * HH + k] = a;
    }
    if (threadIdx.x == 0) {
        float a = bo[o];
        for (int d = 0; d < DD; d++) a += swo[d] * bd[d];
        g_bcomb[o] = a;
    }
}

__global__ void init_kernel() {
    int idx = blockIdx.x * blockDim.x + threadIdx.x;
    if (idx < HF_T) g_h0f[idx] = 0.0f;
    if (idx == 0) { g_count = 0; g_gen = 0; }
}

// ---------------- global software barrier ----------------------------------------------
__device__ __forceinline__ void gbar(unsigned target) {
    __syncthreads();
    if (threadIdx.x == 0) {
        __threadfence();
        unsigned prev = atomicAdd(&g_count, 1);
        if (prev == NCTA - 1) {
            g_count = 0;
            __threadfence();
            g_gen = target;
        } else {
            while (g_gen < target) __nanosleep(32);
        }
        __threadfence();
    }
    __syncthreads();
}

// ---------------- persistent recurrence: warp-specialized bulk-copy + tf32 mma ---------
// 128 CTAs x 256 thr. CTA jt owns cols c = gate*8+uu (Whh row j = gate*1024 + jt*8 + uu).
// Warps 0-3: MMA consumers, warp w owns rows 32w..32w+31 (mt = 2w, 2w+1).
// Thread 128: producer, 16 bulk copies of 32KB per step (A stages, double-buffered).
// Warps 4-7: LSTM pointwise (thread b = tid-128), cell state in registers,
//            h written tf32-rounded in A-fragment layout (kb slab = jt).
__global__ __launch_bounds__(256, 1) void rnn4_kernel(const int* __restrict__ x,
                                                      const float* __restrict__ Whh) {
    extern __shared__ char smraw[];
    uint32_t sb0 = smem_u32(smraw);
    uint32_t sb = (sb0 + 1023u) & ~1023u;
    char* smem = smraw + (sb - sb0);
    float* Cs = (float*)(smem + SM_CS);

    const int tid = threadIdx.x;
    const int jt  = blockIdx.x;
    const int w   = tid >> 5;
    const int l   = tid & 31;

    // ---- pack B fragments (tf32-rounded): [kb][np][lane] 16B ----
    {
        float4* Bp = (float4*)(smem + SM_B);
        for (int i = tid; i < 8192; i += 256) {
            int kb = i >> 6;
            int np = (i >> 5) & 1;
            int L  = i & 31;
            int tig = L & 3, g0 = L >> 2;
            int j0 = (2 * np) * 1024 + jt * 8 + g0;
            int j1 = j0 + 1024;
            int k0 = kb * 8 + tig;
            float4 v;
            v.x = __uint_as_float(f2tf32(Whh[(size_t)j0 * HH + k0]));
            v.y = __uint_as_float(f2tf32(Whh[(size_t)j0 * HH + k0 + 4]));
            v.z = __uint_as_float(f2tf32(Whh[(size_t)j1 * HH + k0]));
            v.w = __uint_as_float(f2tf32(Whh[(size_t)j1 * HH + k0 + 4]));
            Bp[i] = v;
        }
    }
    if (tid == 0) {
        MBAR_INIT(sb + SM_CTL + 0, 1);    // full buf0
        MBAR_INIT(sb + SM_CTL + 8, 1);    // full buf1
        MBAR_INIT(sb + SM_CTL + 16, 4);   // free buf0 (4 consumer warps)
        MBAR_INIT(sb + SM_CTL + 24, 4);   // free buf1
    }

    float creg[8] = {0.f, 0.f, 0.f, 0.f, 0.f, 0.f, 0.f, 0.f};

    gbar(1);

    for (int t = 0; t < TT; t++) {
        if (w < 4) {
            // ================= MMA consumers =================
            float acc[2][4][4];
#pragma unroll
            for (int m = 0; m < 2; m++)
#pragma unroll
                for (int n = 0; n < 4; n++)
#pragma unroll
                    for (int q = 0; q < 4; q++) acc[m][n][q] = 0.f;

            for (int s = 0; s < 16; s++) {
                unsigned u = (unsigned)(t * 8 + (s >> 1));
                MBAR_WAIT(sb + SM_CTL + (s & 1) * 8, u & 1u);
                uint32_t abase = sb + SM_A + (s & 1) * 32768;
#pragma unroll
                for (int kbi = 0; kbi < 8; kbi++) {
                    int kb = s * 8 + kbi;
                    uint32_t aaddr = abase + (uint32_t)(((kbi * 8 + 2 * w) * 32 + l) * 16);
                    uint32_t baddr = sb + SM_B + (uint32_t)(((kb * 2) * 32 + l) * 16);
                    uint32_t a0[4], a1[4], b0[4], b1[4];
                    LDS128(a0, aaddr);
                    LDS128(a1, aaddr + 512);
                    LDS128(b0, baddr);
                    LDS128(b1, baddr + 512);
                    MMA_TF32(acc[0][0], a0, b0[0], b0[1]);
                    MMA_TF32(acc[0][1], a0, b0[2], b0[3]);
                    MMA_TF32(acc[0][2], a0, b1[0], b1[1]);
                    MMA_TF32(acc[0][3], a0, b1[2], b1[3]);
                    MMA_TF32(acc[1][0], a1, b0[0], b0[1]);
                    MMA_TF32(acc[1][1], a1, b0[2], b0[3]);
                    MMA_TF32(acc[1][2], a1, b1[0], b1[1]);
                    MMA_TF32(acc[1][3], a1, b1[2], b1[3]);
                }
                if (l == 0) MBAR_ARRIVE(sb + SM_CTL + 16 + (s & 1) * 8);
            }
            // write C tile: row = 32w + mtl*16 + gID (+8), col = nb*8 + 2tig(+1)
            int gID = l >> 2, tig = l & 3;
#pragma unroll
            for (int mtl = 0; mtl < 2; mtl++) {
                int rb = w * 32 + mtl * 16 + gID;
#pragma unroll
                for (int nb = 0; nb < 4; nb++) {
                    *(float2*)&Cs[rb * 36 + nb * 8 + 2 * tig] =
                        make_float2(acc[mtl][nb][0], acc[mtl][nb][1]);
                    *(float2*)&Cs[(rb + 8) * 36 + nb * 8 + 2 * tig] =
                        make_float2(acc[mtl][nb][2], acc[mtl][nb][3]);
                }
            }
        } else if (tid == 128) {
            // ================= producer: 16 bulk copies =================
            const float* src = t ? (g_hsf + (size_t)(t - 1) * HF_T) : g_h0f;
            for (int s = 0; s < 16; s++) {
                unsigned u = (unsigned)(t * 8 + (s >> 1));
                if (u > 0) MBAR_WAIT(sb + SM_CTL + 16 + (s & 1) * 8, (u - 1) & 1u);
                MBAR_EXPECT_TX(sb + SM_CTL + (s & 1) * 8, 32768);
                BULK_CP(sb + SM_A + (s & 1) * 32768, src + s * 8192, 32768,
                        sb + SM_CTL + (s & 1) * 8);
            }
        }
        __syncthreads();

        // ================= pointwise (warps 4-7): thread b = tid-128 ================
        if (w >= 4) {
            int b = tid - 128;
            int tok = __ldg(&x[b * TT + t]);
            const float* gx = g_gx_tab + (size_t)tok * G4H + (jt << 3);
            float gadd[4][8];
#pragma unroll
            for (int gate = 0; gate < 4; gate++) {
                float4 p0 = *(const float4*)(gx + (gate << 10));
                float4 p1 = *(const float4*)(gx + (gate << 10) + 4);
                gadd[gate][0] = p0.x; gadd[gate][1] = p0.y; gadd[gate][2] = p0.z; gadd[gate][3] = p0.w;
                gadd[gate][4] = p1.x; gadd[gate][5] = p1.y; gadd[gate][6] = p1.z; gadd[gate][7] = p1.w;
            }
            if (t > 0) {
                int pt = __ldg(&x[b * TT + t - 1]);
                const float* at = g_attn_tab + (size_t)pt * G4H + (jt << 3);
#pragma unroll
                for (int gate = 0; gate < 4; gate++) {
                    float4 p0 = *(const float4*)(at + (gate << 10));
                    float4 p1 = *(const float4*)(at + (gate << 10) + 4);
                    gadd[gate][0] += p0.x; gadd[gate][1] += p0.y; gadd[gate][2] += p0.z; gadd[gate][3] += p0.w;
                    gadd[gate][4] += p1.x; gadd[gate][5] += p1.y; gadd[gate][6] += p1.z; gadd[gate][7] += p1.w;
                }
            }
            int mt = b >> 4, ri = b & 15;
            float* hdst = g_hsf + ((size_t)t * 128 + jt) * 1024 + mt * 128;
#pragma unroll
            for (int uu = 0; uu < 8; uu++) {
                float gi = Cs[b * 36 + uu]      + gadd[0][uu];
                float gf = Cs[b * 36 + 8 + uu]  + gadd[1][uu];
                float gg = Cs[b * 36 + 16 + uu] + gadd[2][uu];
                float go = Cs[b * 36 + 24 + uu] + gadd[3][uu];
                float cn = sigm(gf) * creg[uu] + sigm(gi) * tanhf(gg);
                float hn = sigm(go) * tanhf(cn);
                creg[uu] = cn;
                int L = (ri & 7) * 4 + (uu & 3);
                int slot = ((uu >= 4) ? 2 : 0) + ((ri >= 8) ? 1 : 0);
                hdst[L * 4 + slot] = __uint_as_float(f2tf32(hn));
            }
            __threadfence();
        }

        gbar((unsigned)(t + 2));
    }
}

// ---------------- epilogue: logits = hs @ Wcomb^T + bcomb, log_softmax -----------------
__global__ __launch_bounds__(256) void out_kernel(float* __restrict__ out) {
    const int r0 = blockIdx.x << 5;
    __shared__ float A[32][36];
    __shared__ float Wsh[32 * 260];

    const int tid = threadIdx.x;
    const int tx = tid & 31, ty = tid >> 5;
    float acc[4][8] = {};

    for (int kc = 0; kc < HH; kc += 32) {
#pragma unroll
        for (int i = 0; i < 4; i++) {
            int idx = tid + (i << 8);
            int rr = idx >> 5, kk = idx & 31;
            int row = r0 + rr;
            int tt = row >> 7, b = row & 127;
            int k = kc + kk;
            int kb = k >> 3, uu = k & 7;
            int mt = b >> 4, ri = b & 15;
            int L = (ri & 7) * 4 + (uu & 3);
            int slot = ((uu >= 4) ? 2 : 0) + ((ri >= 8) ? 1 : 0);
            A[kk][rr] = g_hsf[((size_t)tt * 128 + kb) * 1024 + mt * 128 + L * 4 + slot];
        }
#pragma unroll
        for (int i = 0; i < 32; i++) {
            int idx = tid + (i << 8);
            int col = idx >> 5, kk = idx & 31;
            Wsh[kk * 260 + col] = g_Wcomb[(size_t)col * HH + kc + kk];
        }
        __syncthreads();
#pragma unroll
        for (int kk = 0; kk < 32; kk++) {
            float4 a4 = *(const float4*)&A[kk][ty << 2];
            float4 w0 = *(const float4*)&Wsh[kk * 260 + (tx << 3)];
            float4 w1 = *(const float4*)&Wsh[kk * 260 + (tx << 3) + 4];
            float ar[4] = {a4.x, a4.y, a4.z, a4.w};
            float wr[8] = {w0.x, w0.y, w0.z, w0.w, w1.x, w1.y, w1.z, w1.w};
#pragma unroll
            for (int r = 0; r < 4; r++)
#pragma unroll
                for (int c = 0; c < 8; c++) acc[r][c] += ar[r] * wr[c];
        }
        __syncthreads();
    }

#pragma unroll
    for (int r = 0; r < 4; r++)
#pragma unroll
        for (int c = 0; c < 8; c++) {
            int col = (tx << 3) + c;
            Wsh[((ty << 2) + r) * 260 + col] = acc[r][c] + g_bcomb[col];
        }
    __syncthreads();

    const int lane = tx;
#pragma unroll
    for (int rr = (ty << 2); rr < (ty << 2) + 4; rr++) {
        const float* row = &Wsh[rr * 260];
        float m = -1e30f;
#pragma unroll
        for (int q = 0; q < 8; q++) m = fmaxf(m, row[lane + (q << 5)]);
#pragma unroll
        for (int off = 16; off > 0; off >>= 1) m = fmaxf(m, __shfl_xor_sync(0xffffffffu, m, off));
        float s = 0.0f;
#pragma unroll
        for (int q = 0; q < 8; q++) s += __expf(row[lane + (q << 5)] - m);
#pragma unroll
        for (int off = 16; off > 0; off >>= 1) s += __shfl_xor_sync(0xffffffffu, s, off);
        float lse = m + logf(s);
        int r = r0 + rr;
        int tcur = r >> 7;
        int bcur = r & 127;
        float* dst = out + (((size_t)bcur * TT + tcur) << 8);
#pragma unroll
        for (int q = 0; q < 8; q++) {
            int vv = lane + (q << 5);
            dst[vv] = row[vv] - lse;
        }
    }
}

// ---------------------------------------------------------------------------------------
extern "C" void kernel_launch(void* const* d_in, const int* in_sizes, int n_in,
                              void* d_out, int out_size) {
    const int*   x        = (const int*)  d_in[0];
    const float* emb      = (const float*)d_in[1];
    const float* lstm_Wih = (const float*)d_in[2];
    const float* lstm_Whh = (const float*)d_in[3];
    const float* lstm_bih = (const float*)d_in[4];
    const float* lstm_bhh = (const float*)d_in[5];
    const float* Wd       = (const float*)d_in[6];
    const float* bd       = (const float*)d_in[7];
    const float* Wo       = (const float*)d_in[8];
    const float* bo       = (const float*)d_in[9];
    const float* s1_Wih   = (const float*)d_in[10];
    const float* s1_bih   = (const float*)d_in[11];
    const float* s1_bhh   = (const float*)d_in[12];
    const float* s1_Wd    = (const float*)d_in[13];
    const float* s1_bd    = (const float*)d_in[14];
    const float* s2_Wih   = (const float*)d_in[15];
    const float* s2_bih   = (const float*)d_in[16];
    const float* s2_bhh   = (const float*)d_in[17];
    const float* s2_Wd    = (const float*)d_in[18];
    const float* s2_bd    = (const float*)d_in[19];
    float* out = (float*)d_out;

    const int smem_bytes = SM_TOTAL + 1024;
    cudaFuncSetAttribute(rnn4_kernel, cudaFuncAttributeMaxDynamicSharedMemorySize, smem_bytes);

    senti_tab_kernel<<<1, 256>>>(emb, s1_Wih, s1_bih, s1_bhh, s1_Wd, s1_bd,
                                 s2_Wih, s2_bih, s2_bhh, s2_Wd, s2_bd);
    tab_kernel<<<VV, 256>>>(emb, lstm_Wih, lstm_bih, lstm_bhh);
    wcomb_kernel<<<VV, 256>>>(Wd, bd, Wo, bo);
    init_kernel<<<(HF_T + 255) / 256, 256>>>();

    rnn4_kernel<<<NCTA, 256, smem_bytes>>>(x, lstm_Whh);

    out_kernel<<<(TT * BB) / 32, 256>>>(out);
}